// round 16
// baseline (speedup 1.0000x reference)
#include <cuda_runtime.h>
#include <cuda_bf16.h>
#include <cstdint>

#define Tn 512
#define Bn 2
#define Hn 128
#define En 32
#define Vn 32000
#define KF 384   // feature dim: 3 * Hn

// ---------------- scratch (no allocations allowed) ----------------
__device__ __align__(16) float g_xp[Bn * Tn * Hn];
__device__ __align__(16) float g_rnn[Bn * Tn * Hn];
__device__ __align__(16) float g_q[Bn * Tn * Hn];
__device__ __align__(16) float g_k[Bn * Tn * Hn];
__device__ __align__(16) float g_proj[Bn * Tn * Hn];
__device__ __align__(16) float g_F[Bn * Tn * KF];
__device__ __align__(16) float g_G[Bn * Tn * KF];
__device__ float g_c[Bn * Tn];
__device__ float g_d[Bn * Tn];
__device__ __align__(16) float g_S[Bn * Tn * Tn];
__device__ __align__(16) float g_ctx[Bn * Tn * Hn];
__device__ __align__(16) __nv_bfloat16 g_wh[(size_t)Vn * Hn];  // Wfc hi
__device__ __align__(16) __nv_bfloat16 g_wl[(size_t)Vn * Hn];  // Wfc lo
__device__ __align__(16) __nv_bfloat16 g_ph[Bn * Tn * Hn];     // proj hi
__device__ __align__(16) __nv_bfloat16 g_pl[Bn * Tn * Hn];     // proj lo

// ---------------- f32x2 packed-FMA helpers ----------------
#define FMA_F32X2(d, a, b, c) \
    asm("fma.rn.f32x2 %0, %1, %2, %3;" : "=l"(d) : "l"(a), "l"(b), "l"(c))
__device__ __forceinline__ float f2sum(unsigned long long p) {
    float lo, hi;
    asm("mov.b64 {%0, %1}, %2;" : "=f"(lo), "=f"(hi) : "l"(p));
    return lo + hi;
}

__device__ __forceinline__ float fast_tanh(float x) {
    x = fminf(fmaxf(x, -15.f), 15.f);
    float e = __expf(2.f * x);
    return __fdividef(e - 1.f, e + 1.f);
}
#define TANH_C1 (-0.33333333f)
#define TANH_C2 (0.13333334f)
#define TANH_C3 (-0.05396825f)
#define TANH_C4 (0.02186949f)
__device__ __forceinline__ float poly_tanh(float x) {
    float u = x * x;
    float p = fmaf(u, TANH_C4, TANH_C3);
    p = fmaf(u, p, TANH_C2);
    p = fmaf(u, p, TANH_C1);
    p = fmaf(u, p, 1.0f);
    return x * p;
}

// ---------------- mma.sync / ldmatrix helpers (sm_80-era: legal on compute_103) ----------------
__device__ __forceinline__ uint32_t smem_u32(const void* p) {
    uint32_t a;
    asm("{ .reg .u64 t; cvta.to.shared.u64 t, %1; cvt.u32.u64 %0, t; }" : "=r"(a) : "l"(p));
    return a;
}
#define LDMX4(r, addr) \
    asm volatile("ldmatrix.sync.aligned.m8n8.x4.shared.b16 {%0,%1,%2,%3}, [%4];" \
        : "=r"((r)[0]), "=r"((r)[1]), "=r"((r)[2]), "=r"((r)[3]) : "r"(addr))
#define MMA16816(d, a, b) \
    asm volatile("mma.sync.aligned.m16n8k16.row.col.f32.bf16.bf16.f32 " \
        "{%0,%1,%2,%3}, {%4,%5,%6,%7}, {%8,%9}, {%0,%1,%2,%3};" \
        : "+f"((d)[0]), "+f"((d)[1]), "+f"((d)[2]), "+f"((d)[3]) \
        : "r"((a)[0]), "r"((a)[1]), "r"((a)[2]), "r"((a)[3]), "r"((b)[0]), "r"((b)[1]))

// ---------------- K1: embedding + input projection ----------------
__global__ void k_embed(const unsigned* __restrict__ xw,
                        const float* __restrict__ etab,
                        const float* __restrict__ W_ih,
                        const float* __restrict__ b_ih,
                        const float* __restrict__ b_hh) {
    int bt = blockIdx.x;
    int h = threadIdx.x;
    int nz = 0;
    for (int i = threadIdx.x; i < 512; i += 128)
        nz |= (xw[2 * i + 1] != 0u);
    int is32 = __syncthreads_or(nz);

    __shared__ float emb[En];
    __shared__ int sidx;
    if (threadIdx.x == 0) {
        long long idx;
        if (is32) idx = (long long)(((const int*)xw)[bt]);
        else      idx = ((const long long*)xw)[bt];
        sidx = (int)idx;
    }
    __syncthreads();
    if (h < En) emb[h] = etab[(long long)sidx * En + h];
    __syncthreads();
    float acc = b_ih[h] + b_hh[h];
#pragma unroll
    for (int e = 0; e < En; e++) acc = fmaf(emb[e], W_ih[h * En + e], acc);
    g_xp[bt * Hn + h] = acc;
}

// ---------------- K2: RNN scan ----------------
__global__ void __launch_bounds__(128, 1) k_rnn(const float* __restrict__ hidden,
                                                const float* __restrict__ W_hh,
                                                float* __restrict__ out_hidden) {
    int b = blockIdx.x;
    int j = threadIdx.x;
    unsigned long long w2[64];
    const unsigned long long* wrow = (const unsigned long long*)(W_hh + j * Hn);
#pragma unroll
    for (int q = 0; q < 64; q++) w2[q] = wrow[q];

    __shared__ __align__(16) float hbuf[2][Hn];
    hbuf[0][j] = hidden[b * Hn + j];
    __syncthreads();

    const float* xp = g_xp + b * Tn * Hn;
    float* rnn = g_rnn + b * Tn * Hn;
    float xv_next = xp[j];
    for (int t = 0; t < Tn; t++) {
        float xv = xv_next;
        if (t + 1 < Tn) xv_next = xp[(t + 1) * Hn + j];
        const ulonglong2* h2 = (const ulonglong2*)hbuf[t & 1];
        unsigned long long a0 = 0ull, a1 = 0ull, a2 = 0ull, a3 = 0ull;
#pragma unroll
        for (int q = 0; q < 32; q += 2) {
            ulonglong2 hv0 = h2[q];
            ulonglong2 hv1 = h2[q + 1];
            FMA_F32X2(a0, w2[2 * q + 0], hv0.x, a0);
            FMA_F32X2(a1, w2[2 * q + 1], hv0.y, a1);
            FMA_F32X2(a2, w2[2 * q + 2], hv1.x, a2);
            FMA_F32X2(a3, w2[2 * q + 3], hv1.y, a3);
        }
        float s = (f2sum(a0) + f2sum(a1)) + (f2sum(a2) + f2sum(a3)) + xv;
        float hn = poly_tanh(s);
        if (__any_sync(0xffffffffu, fabsf(s) > 0.55f)) hn = fast_tanh(s);
        hbuf[(t + 1) & 1][j] = hn;
        rnn[t * Hn + j] = hn;
        __syncthreads();
    }
    out_hidden[b * Hn + j] = hbuf[0][j];
}

// ---------------- K3: q/k projections ----------------
__global__ void __launch_bounds__(128) k_qk(const float* __restrict__ W1,
                                            const float* __restrict__ W2) {
    __shared__ float a_s[128][34];
    __shared__ float b_s[128][36];
    int tid = threadIdx.x;
    int tx = tid & 7, ty = tid >> 3;
    int n0 = blockIdx.x * 32, m0 = blockIdx.y * 32;
    const float* W = (n0 < Hn) ? W1 : W2;
    int nb = n0 & (Hn - 1);

    for (int idx = tid; idx < 32 * 128; idx += 128) {
        int r = idx >> 7, k = idx & 127;
        a_s[k][r] = g_rnn[(m0 + r) * Hn + k];
        b_s[k][r] = W[(nb + r) * Hn + k];
    }
    __syncthreads();

    float acc[2][4];
#pragma unroll
    for (int i = 0; i < 2; i++)
#pragma unroll
        for (int jj = 0; jj < 4; jj++) acc[i][jj] = 0.f;
#pragma unroll 4
    for (int k = 0; k < 128; k++) {
        float2 av = *(const float2*)&a_s[k][ty * 2];
        float4 bv = *(const float4*)&b_s[k][tx * 4];
        acc[0][0] = fmaf(av.x, bv.x, acc[0][0]);
        acc[0][1] = fmaf(av.x, bv.y, acc[0][1]);
        acc[0][2] = fmaf(av.x, bv.z, acc[0][2]);
        acc[0][3] = fmaf(av.x, bv.w, acc[0][3]);
        acc[1][0] = fmaf(av.y, bv.x, acc[1][0]);
        acc[1][1] = fmaf(av.y, bv.y, acc[1][1]);
        acc[1][2] = fmaf(av.y, bv.z, acc[1][2]);
        acc[1][3] = fmaf(av.y, bv.w, acc[1][3]);
    }
    float* dst = (n0 < Hn) ? g_q : g_k;
#pragma unroll
    for (int i = 0; i < 2; i++) {
        float4 o = {acc[i][0], acc[i][1], acc[i][2], acc[i][3]};
        *(float4*)&dst[(m0 + ty * 2 + i) * Hn + nb + tx * 4] = o;
    }
}

// ---------------- K4a: separable tanh features ----------------
__global__ void __launch_bounds__(128) k_feat(const float* __restrict__ v) {
    int bt = blockIdx.x;
    int tid = threadIdx.x;
    float q = g_q[bt * Hn + tid], k = g_k[bt * Hn + tid], vv = v[tid];
    float A = poly_tanh(q), B = poly_tanh(k);
    if (__any_sync(0xffffffffu, fmaxf(fabsf(q), fabsf(k)) > 0.55f)) {
        A = fast_tanh(q);
        B = fast_tanh(k);
    }
    float A2 = A * A, B2 = B * B;
    int fb = bt * KF + tid;
    g_F[fb] = -vv * A2;
    g_F[fb + 128] = vv * (A2 * A - A);
    g_F[fb + 256] = vv * A2;
    g_G[fb] = B;
    g_G[fb + 128] = B2;
    g_G[fb + 256] = B2 * B;

    float c = vv * A, d = vv * B;
#pragma unroll
    for (int off = 16; off; off >>= 1) {
        c += __shfl_xor_sync(0xffffffffu, c, off);
        d += __shfl_xor_sync(0xffffffffu, d, off);
    }
    __shared__ float rc[4], rd[4];
    int w = tid >> 5;
    if ((tid & 31) == 0) { rc[w] = c; rd[w] = d; }
    __syncthreads();
    if (tid == 0) {
        g_c[bt] = rc[0] + rc[1] + rc[2] + rc[3];
        g_d[bt] = rd[0] + rd[1] + rd[2] + rd[3];
    }
}

// ---------------- K4b: score GEMM ----------------
__global__ void __launch_bounds__(256) k_score() {
    int sx = blockIdx.x, tyb = blockIdx.y, b = blockIdx.z;
    if (sx > tyb) return;
    int n0 = sx * 64, m0 = tyb * 64, boff = b * Tn;
    __shared__ float a_s[64][68];
    __shared__ float b_s[64][68];
    int tid = threadIdx.x;
    int tx = tid & 15, ty = tid >> 4;
    float acc[4][4];
#pragma unroll
    for (int i = 0; i < 4; i++)
#pragma unroll
        for (int j = 0; j < 4; j++) acc[i][j] = 0.f;

    for (int kc = 0; kc < KF / 64; kc++) {
        for (int idx = tid; idx < 64 * 64; idx += 256) {
            int r = idx >> 6, k = idx & 63;
            a_s[k][r] = g_F[(boff + m0 + r) * KF + kc * 64 + k];
            b_s[k][r] = g_G[(boff + n0 + r) * KF + kc * 64 + k];
        }
        __syncthreads();
#pragma unroll 8
        for (int k = 0; k < 64; k++) {
            float4 av = *(const float4*)&a_s[k][ty * 4];
            float4 bv = *(const float4*)&b_s[k][tx * 4];
            float a[4] = {av.x, av.y, av.z, av.w};
            float bb[4] = {bv.x, bv.y, bv.z, bv.w};
#pragma unroll
            for (int i = 0; i < 4; i++)
#pragma unroll
                for (int j = 0; j < 4; j++)
                    acc[i][j] = fmaf(a[i], bb[j], acc[i][j]);
        }
        __syncthreads();
    }
    float dv0 = g_d[boff + n0 + tx * 4], dv1 = g_d[boff + n0 + tx * 4 + 1];
    float dv2 = g_d[boff + n0 + tx * 4 + 2], dv3 = g_d[boff + n0 + tx * 4 + 3];
#pragma unroll
    for (int i = 0; i < 4; i++) {
        float ci = g_c[boff + m0 + ty * 4 + i];
        float4 o = {acc[i][0] + ci + dv0, acc[i][1] + ci + dv1,
                    acc[i][2] + ci + dv2, acc[i][3] + ci + dv3};
        *(float4*)&g_S[(size_t)(boff + m0 + ty * 4 + i) * Tn + n0 + tx * 4] = o;
    }
}

// ---------------- K4c: causal softmax ----------------
__global__ void __launch_bounds__(256) k_softmax(float* __restrict__ out_w) {
    int bt = blockIdx.x;
    int t = bt & 511;
    int tid = threadIdx.x;
    float* row = g_S + (size_t)bt * Tn;
    __shared__ float sc[Tn];
    __shared__ float red[256];

    float m = -1e30f;
    for (int s = tid; s <= t; s += 256) m = fmaxf(m, row[s]);
    red[tid] = m;
    __syncthreads();
    for (int st = 128; st; st >>= 1) {
        if (tid < st) red[tid] = fmaxf(red[tid], red[tid + st]);
        __syncthreads();
    }
    float mx = red[0];
    __syncthreads();
    float ssum = 0.f;
    for (int s = tid; s <= t; s += 256) {
        float e = __expf(row[s] - mx);
        sc[s] = e;
        ssum += e;
    }
    red[tid] = ssum;
    __syncthreads();
    for (int st = 128; st; st >>= 1) {
        if (tid < st) red[tid] += red[tid + st];
        __syncthreads();
    }
    float rinv = __fdividef(1.f, red[0]);
    __syncthreads();
    for (int s = tid; s < Tn; s += 256) {
        float wv = (s <= t) ? sc[s] * rinv : 0.f;
        out_w[(size_t)bt * Tn + s] = wv;
        row[s] = wv;
    }
}

// ---------------- K4d: context GEMM ----------------
__global__ void __launch_bounds__(128) k_ctx() {
    int n0 = blockIdx.x * 32;
    int m0 = blockIdx.y * 32;
    int b = blockIdx.z;
    __shared__ float a_s[128][34];
    __shared__ float b_s[128][36];
    int tid = threadIdx.x;
    int tx = tid & 7, ty = tid >> 3;
    float acc[2][4];
#pragma unroll
    for (int i = 0; i < 2; i++)
#pragma unroll
        for (int j = 0; j < 4; j++) acc[i][j] = 0.f;

    for (int kc = 0; kc < 4; kc++) {
        for (int idx = tid; idx < 32 * 128; idx += 128) {
            int r = idx >> 7, k = idx & 127;
            a_s[k][r] = g_S[(size_t)(b * Tn + m0 + r) * Tn + kc * 128 + k];
        }
        for (int idx = tid; idx < 32 * 128; idx += 128) {
            int k = idx >> 5, r = idx & 31;
            b_s[k][r] = g_rnn[(b * Tn + kc * 128 + k) * Hn + n0 + r];
        }
        __syncthreads();
#pragma unroll 4
        for (int k = 0; k < 128; k++) {
            float2 av = *(const float2*)&a_s[k][ty * 2];
            float4 bv = *(const float4*)&b_s[k][tx * 4];
            acc[0][0] = fmaf(av.x, bv.x, acc[0][0]);
            acc[0][1] = fmaf(av.x, bv.y, acc[0][1]);
            acc[0][2] = fmaf(av.x, bv.z, acc[0][2]);
            acc[0][3] = fmaf(av.x, bv.w, acc[0][3]);
            acc[1][0] = fmaf(av.y, bv.x, acc[1][0]);
            acc[1][1] = fmaf(av.y, bv.y, acc[1][1]);
            acc[1][2] = fmaf(av.y, bv.z, acc[1][2]);
            acc[1][3] = fmaf(av.y, bv.w, acc[1][3]);
        }
        __syncthreads();
    }
#pragma unroll
    for (int i = 0; i < 2; i++) {
        float4 o = {acc[i][0], acc[i][1], acc[i][2], acc[i][3]};
        *(float4*)&g_ctx[(b * Tn + m0 + ty * 2 + i) * Hn + n0 + tx * 4] = o;
    }
}

// ---------------- K4e: proj GEMM (+ bf16 hi/lo copies for the MMA logits) ----------------
__global__ void __launch_bounds__(128) k_proj(const float* __restrict__ Wp,
                                              const float* __restrict__ bp) {
    int n0 = blockIdx.x * 32;
    int m0 = blockIdx.y * 32;
    __shared__ float a_s[128][34];
    __shared__ float b_s[128][36];
    int tid = threadIdx.x;
    int tx = tid & 7, ty = tid >> 3;
    float acc[2][4];
#pragma unroll
    for (int i = 0; i < 2; i++)
#pragma unroll
        for (int j = 0; j < 4; j++) acc[i][j] = 0.f;

    for (int ch = 0; ch < 2; ch++) {
        const float* src = ch ? g_ctx : g_rnn;
        for (int idx = tid; idx < 32 * 128; idx += 128) {
            int r = idx >> 7, k = idx & 127;
            a_s[k][r] = src[(m0 + r) * Hn + k];
            b_s[k][r] = Wp[(n0 + r) * (2 * Hn) + ch * Hn + k];
        }
        __syncthreads();
#pragma unroll 4
        for (int k = 0; k < 128; k++) {
            float2 av = *(const float2*)&a_s[k][ty * 2];
            float4 bv = *(const float4*)&b_s[k][tx * 4];
            acc[0][0] = fmaf(av.x, bv.x, acc[0][0]);
            acc[0][1] = fmaf(av.x, bv.y, acc[0][1]);
            acc[0][2] = fmaf(av.x, bv.z, acc[0][2]);
            acc[0][3] = fmaf(av.x, bv.w, acc[0][3]);
            acc[1][0] = fmaf(av.y, bv.x, acc[1][0]);
            acc[1][1] = fmaf(av.y, bv.y, acc[1][1]);
            acc[1][2] = fmaf(av.y, bv.z, acc[1][2]);
            acc[1][3] = fmaf(av.y, bv.w, acc[1][3]);
        }
        __syncthreads();
    }
    float4 bpv = *(const float4*)&bp[n0 + tx * 4];
    float bb[4] = {bpv.x, bpv.y, bpv.z, bpv.w};
#pragma unroll
    for (int i = 0; i < 2; i++) {
        float4 o = {fmaxf(acc[i][0] + bb[0], 0.f), fmaxf(acc[i][1] + bb[1], 0.f),
                    fmaxf(acc[i][2] + bb[2], 0.f), fmaxf(acc[i][3] + bb[3], 0.f)};
        int row = m0 + ty * 2 + i, cb = n0 + tx * 4;
        *(float4*)&g_proj[row * Hn + cb] = o;
        __nv_bfloat16 h0 = __float2bfloat16(o.x), h1 = __float2bfloat16(o.y);
        __nv_bfloat16 h2 = __float2bfloat16(o.z), h3 = __float2bfloat16(o.w);
        __nv_bfloat162 hh0, hh1, ll0, ll1;
        hh0.x = h0; hh0.y = h1; hh1.x = h2; hh1.y = h3;
        ll0.x = __float2bfloat16(o.x - __bfloat162float(h0));
        ll0.y = __float2bfloat16(o.y - __bfloat162float(h1));
        ll1.x = __float2bfloat16(o.z - __bfloat162float(h2));
        ll1.y = __float2bfloat16(o.w - __bfloat162float(h3));
        *(__nv_bfloat162*)&g_ph[row * Hn + cb] = hh0;
        *(__nv_bfloat162*)&g_ph[row * Hn + cb + 2] = hh1;
        *(__nv_bfloat162*)&g_pl[row * Hn + cb] = ll0;
        *(__nv_bfloat162*)&g_pl[row * Hn + cb + 2] = ll1;
    }
}

// ---------------- K5a: Wfc fp32 -> bf16 hi/lo split ----------------
__global__ void __launch_bounds__(256) k_wconv(const float* __restrict__ Wfc) {
    size_t i = (size_t)blockIdx.x * 256 + threadIdx.x;  // float4 index
    float4 w = ((const float4*)Wfc)[i];
    __nv_bfloat16 h0 = __float2bfloat16(w.x), h1 = __float2bfloat16(w.y);
    __nv_bfloat16 h2 = __float2bfloat16(w.z), h3 = __float2bfloat16(w.w);
    __nv_bfloat162 hh0, hh1, ll0, ll1;
    hh0.x = h0; hh0.y = h1; hh1.x = h2; hh1.y = h3;
    ll0.x = __float2bfloat16(w.x - __bfloat162float(h0));
    ll0.y = __float2bfloat16(w.y - __bfloat162float(h1));
    ll1.x = __float2bfloat16(w.z - __bfloat162float(h2));
    ll1.y = __float2bfloat16(w.w - __bfloat162float(h3));
    ((__nv_bfloat162*)g_wh)[i * 2] = hh0;
    ((__nv_bfloat162*)g_wh)[i * 2 + 1] = hh1;
    ((__nv_bfloat162*)g_wl)[i * 2] = ll0;
    ((__nv_bfloat162*)g_wl)[i * 2 + 1] = ll1;
}

// ---------------- K5b: logits GEMM on mma.sync, 2 blocks/SM ----------------
// C[1024,32000] = proj @ Wfc^T + bfc.  128x128 tile, 8 warps (4m x 2n).
// B tiles (Wfc hi/lo) staged in smem (LROW=272: conflict-free ldmatrix);
// A fragments loaded DIRECTLY from g_ph/g_pl (per-lane 32-bit LDG, L1-hot
// since consecutive blocks share m0).  smem 69.6KB -> 2 blocks/SM so one
// block's B-fill overlaps the other's MMA work.
#define LROW 272
#define SM_BH 0
#define SM_BL 34816
#define SM_TOT 69632
__global__ void __launch_bounds__(256, 2) k_logits_mma(const float* __restrict__ bfc,
                                                       float* __restrict__ logits) {
    extern __shared__ char smem[];
    uint32_t sb = smem_u32(smem);
    int tid = threadIdx.x;
    int lane = tid & 31, wid = tid >> 5;
    int wr = wid & 3, wc = wid >> 2;
    int m0 = blockIdx.y * 128, n0 = blockIdx.x * 128;

    // stage B tiles only (hi/lo): 128 rows x 256B payload each
    for (int idx = tid; idx < 128 * 16; idx += 256) {
        int row = idx >> 4, q = idx & 15;
        *(uint4*)(smem + SM_BH + row * LROW + q * 16) =
            ((const uint4*)(g_wh + (size_t)(n0 + row) * Hn))[q];
        *(uint4*)(smem + SM_BL + row * LROW + q * 16) =
            ((const uint4*)(g_wl + (size_t)(n0 + row) * Hn))[q];
    }
    __syncthreads();

    float d[2][8][4];
#pragma unroll
    for (int mf = 0; mf < 2; mf++)
#pragma unroll
        for (int nf = 0; nf < 8; nf++)
#pragma unroll
            for (int e = 0; e < 4; e++) d[mf][nf][e] = 0.f;

    int lrow = lane & 15;
    int lkoff = (lane >> 4) * 16;
    // A fragment row pointers (u32 = 2 packed bf16); frag col u32-index = ks*8 + (lane&3)
    int ar = m0 + wr * 32 + (lane >> 2);
    const uint32_t* pAh0 = (const uint32_t*)(g_ph + (size_t)ar * Hn);
    const uint32_t* pAl0 = (const uint32_t*)(g_pl + (size_t)ar * Hn);
    int ac = lane & 3;
    const int r8 = 8 * Hn / 2, mf16 = 16 * Hn / 2;  // u32 strides

#pragma unroll
    for (int ks = 0; ks < 8; ks++) {
        uint32_t ah[2][4], al[2][4];
        int cb = ks * 8 + ac;
#pragma unroll
        for (int mf = 0; mf < 2; mf++) {
            const uint32_t* ph = pAh0 + mf * mf16;
            const uint32_t* pl = pAl0 + mf * mf16;
            ah[mf][0] = ph[cb];           // (r,      k0-1)
            ah[mf][1] = ph[r8 + cb];      // (r+8,    k0-1)
            ah[mf][2] = ph[cb + 4];       // (r,      k8-9)
            ah[mf][3] = ph[r8 + cb + 4];  // (r+8,    k8-9)
            al[mf][0] = pl[cb];
            al[mf][1] = pl[r8 + cb];
            al[mf][2] = pl[cb + 4];
            al[mf][3] = pl[r8 + cb + 4];
        }
#pragma unroll
        for (int p = 0; p < 4; p++) {
            uint32_t bd = sb + SM_BH + (wc * 64 + p * 16 + lrow) * LROW + ks * 32 + lkoff;
            uint32_t th[4], tl[4];
            LDMX4(th, bd);
            LDMX4(tl, bd + (SM_BL - SM_BH));
            uint32_t bh0[2] = {th[0], th[2]}, bh1[2] = {th[1], th[3]};
            uint32_t bl0[2] = {tl[0], tl[2]}, bl1[2] = {tl[1], tl[3]};
#pragma unroll
            for (int mf = 0; mf < 2; mf++) {
                MMA16816(d[mf][2 * p], ah[mf], bh0);
                MMA16816(d[mf][2 * p], ah[mf], bl0);
                MMA16816(d[mf][2 * p], al[mf], bh0);
                MMA16816(d[mf][2 * p + 1], ah[mf], bh1);
                MMA16816(d[mf][2 * p + 1], ah[mf], bl1);
                MMA16816(d[mf][2 * p + 1], al[mf], bh1);
            }
        }
    }

    // epilogue: bias + direct float2 stores (fragment layout)
    int gq = lane >> 2, tig = lane & 3;
#pragma unroll
    for (int nf = 0; nf < 8; nf++) {
        int ncol = n0 + wc * 64 + nf * 8 + tig * 2;
        float2 bb = *(const float2*)&bfc[ncol];
#pragma unroll
        for (int mf = 0; mf < 2; mf++) {
            int r = m0 + wr * 32 + mf * 16 + gq;
            float2 o0 = {d[mf][nf][0] + bb.x, d[mf][nf][1] + bb.y};
            float2 o1 = {d[mf][nf][2] + bb.x, d[mf][nf][3] + bb.y};
            *(float2*)&logits[(size_t)r * Vn + ncol] = o0;
            *(float2*)&logits[(size_t)(r + 8) * Vn + ncol] = o1;
        }
    }
}

// ---------------- launch ----------------
extern "C" void kernel_launch(void* const* d_in, const int* in_sizes, int n_in,
                              void* d_out, int out_size) {
    const void* x = d_in[0];
    const float* hidden = (const float*)d_in[1];
    const float* etab = (const float*)d_in[2];
    const float* W_ih = (const float*)d_in[3];
    const float* W_hh = (const float*)d_in[4];
    const float* b_ih = (const float*)d_in[5];
    const float* b_hh = (const float*)d_in[6];
    const float* W1 = (const float*)d_in[7];
    const float* W2 = (const float*)d_in[8];
    const float* v = (const float*)d_in[9];
    const float* Wp = (const float*)d_in[10];
    const float* bp = (const float*)d_in[11];
    const float* Wfc = (const float*)d_in[12];
    const float* bfc = (const float*)d_in[13];

    float* out = (float*)d_out;
    float* out_logits = out;
    float* out_hidden = out + (size_t)Bn * Tn * Vn;
    float* out_weights = out_hidden + Bn * Hn;

    static int smem_set = 0;
    if (!smem_set) {
        cudaFuncSetAttribute(k_logits_mma, cudaFuncAttributeMaxDynamicSharedMemorySize, SM_TOT);
        smem_set = 1;
    }

    k_wconv<<<(Vn * Hn) / 4 / 256, 256>>>(Wfc);
    k_embed<<<Bn * Tn, 128>>>((const unsigned*)x, etab, W_ih, b_ih, b_hh);
    k_rnn<<<Bn, 128>>>(hidden, W_hh, out_hidden);
    k_qk<<<dim3(8, 32), 128>>>(W1, W2);
    k_feat<<<Bn * Tn, 128>>>(v);
    k_score<<<dim3(8, 8, Bn), 256>>>();
    k_softmax<<<Bn * Tn, 256>>>(out_weights);
    k_ctx<<<dim3(4, 16, Bn), 128>>>();
    k_proj<<<dim3(4, 32), 128>>>(Wp, bp);
    k_logits_mma<<<dim3(Vn / 128, (Bn * Tn) / 128), 256, SM_TOT>>>(bfc, out_logits);
}